// round 3
// baseline (speedup 1.0000x reference)
#include <cuda_runtime.h>

#define H 2048
#define W 2048
#define HW (H * W)

__device__ __forceinline__ int refl(int i, int n) {
    if (i < 0) return -i;
    if (i >= n) return 2 * n - 2 - i;
    return i;
}

// Streaming store: evict-first in L2 so the 192MB output stream doesn't
// thrash the 64MB input (which then stays L2-resident across the kernel).
__device__ __forceinline__ void stcs4(float* p, float a, float b, float c, float d) {
    float4 v = make_float4(a, b, c, d);
    asm volatile("st.global.cs.v4.f32 [%0], {%1,%2,%3,%4};"
                 :: "l"(p), "f"(v.x), "f"(v.y), "f"(v.z), "f"(v.w) : "memory");
}

__global__ __launch_bounds__(128, 12) void demosaic_kernel(
    const float* __restrict__ x, float* __restrict__ out)
{
    const int tx = blockIdx.x * blockDim.x + threadIdx.x;  // 0..511  (4 cols each)
    const int ty = blockIdx.y * blockDim.y + threadIdx.y;  // 0..1023 (2 rows each)
    const int n  = blockIdx.z;                             // batch 0..3

    const int col0 = tx * 4;
    const int row0 = ty * 2;

    const float* __restrict__ xp = x + (size_t)n * HW;

    // Window: rows row0-2 .. row0+3 (6), cols col0-4 .. col0+7 (12, float4-aligned).
    float v[6][12];

    const bool interior = (row0 >= 2) && (row0 <= H - 6) &&
                          (col0 >= 4) && (col0 <= W - 8);

    if (interior) {
#pragma unroll
        for (int r = 0; r < 6; r++) {
            const float4* p = reinterpret_cast<const float4*>(
                xp + (size_t)(row0 - 2 + r) * W + (col0 - 4));
            float4 a = __ldg(p);
            float4 b = __ldg(p + 1);
            float4 c = __ldg(p + 2);
            v[r][0] = a.x; v[r][1] = a.y; v[r][2]  = a.z; v[r][3]  = a.w;
            v[r][4] = b.x; v[r][5] = b.y; v[r][6]  = b.z; v[r][7]  = b.w;
            v[r][8] = c.x; v[r][9] = c.y; v[r][10] = c.z; v[r][11] = c.w;
        }
    } else {
        // Border: scalar loads with reflect indexing (mode="reflect", no edge repeat).
#pragma unroll
        for (int r = 0; r < 6; r++) {
            const int rr = refl(row0 - 2 + r, H);
            const float* rowp = xp + (size_t)rr * W;
#pragma unroll
            for (int ci = 0; ci < 12; ci++) {
                const int cc = refl(col0 - 4 + ci, W);
                v[r][ci] = __ldg(rowp + cc);
            }
        }
    }

    // Demosaic 5x5 taps (all /8), factored into shared sub-sums:
    //   kgrb  = (4c + 2(v1+h1) - (v2+h2)) / 8
    //   krbbr = (6c + 2*diag - 1.5(v2+h2)) / 8
    //   krbg0 = (5c + 4h1 - diag + 0.5 v2 - h2) / 8
    //   krbg1 = (5c + 4v1 - diag + 0.5 h2 - v2) / 8
    float R[2][4], G[2][4], B[2][4];

#pragma unroll
    for (int pr = 0; pr < 2; pr++) {
#pragma unroll
        for (int pc = 0; pc < 4; pc++) {
            const int r = 2 + pr;
            const int c = 4 + pc;
            const float ctr = v[r][c];
            float rr, gg, bb;

            if ((pr & 1) == 0 && (pc & 1) == 0) {
                // R site: G=kgrb, B=krbbr
                const float v1 = v[r - 1][c] + v[r + 1][c];
                const float h1 = v[r][c - 1] + v[r][c + 1];
                const float ax2 = v[r - 2][c] + v[r + 2][c] + v[r][c - 2] + v[r][c + 2];
                const float dg = v[r - 1][c - 1] + v[r - 1][c + 1] +
                                 v[r + 1][c - 1] + v[r + 1][c + 1];
                rr = ctr;
                gg = 0.125f * (4.0f * ctr + 2.0f * (v1 + h1) - ax2);
                bb = 0.125f * (6.0f * ctr + 2.0f * dg - 1.5f * ax2);
            } else if ((pr & 1) == 0) {
                // G site on R row: R=krbg0, B=krbg1
                const float v1 = v[r - 1][c] + v[r + 1][c];
                const float h1 = v[r][c - 1] + v[r][c + 1];
                const float v2 = v[r - 2][c] + v[r + 2][c];
                const float h2 = v[r][c - 2] + v[r][c + 2];
                const float dg = v[r - 1][c - 1] + v[r - 1][c + 1] +
                                 v[r + 1][c - 1] + v[r + 1][c + 1];
                rr = 0.125f * (5.0f * ctr + 4.0f * h1 - dg + 0.5f * v2 - h2);
                gg = ctr;
                bb = 0.125f * (5.0f * ctr + 4.0f * v1 - dg + 0.5f * h2 - v2);
            } else if ((pc & 1) == 0) {
                // G site on B row: R=krbg1, B=krbg0
                const float v1 = v[r - 1][c] + v[r + 1][c];
                const float h1 = v[r][c - 1] + v[r][c + 1];
                const float v2 = v[r - 2][c] + v[r + 2][c];
                const float h2 = v[r][c - 2] + v[r][c + 2];
                const float dg = v[r - 1][c - 1] + v[r - 1][c + 1] +
                                 v[r + 1][c - 1] + v[r + 1][c + 1];
                rr = 0.125f * (5.0f * ctr + 4.0f * v1 - dg + 0.5f * h2 - v2);
                gg = ctr;
                bb = 0.125f * (5.0f * ctr + 4.0f * h1 - dg + 0.5f * v2 - h2);
            } else {
                // B site: R=krbbr, G=kgrb
                const float v1 = v[r - 1][c] + v[r + 1][c];
                const float h1 = v[r][c - 1] + v[r][c + 1];
                const float ax2 = v[r - 2][c] + v[r + 2][c] + v[r][c - 2] + v[r][c + 2];
                const float dg = v[r - 1][c - 1] + v[r - 1][c + 1] +
                                 v[r + 1][c - 1] + v[r + 1][c + 1];
                rr = 0.125f * (6.0f * ctr + 2.0f * dg - 1.5f * ax2);
                gg = 0.125f * (4.0f * ctr + 2.0f * (v1 + h1) - ax2);
                bb = ctr;
            }

            R[pr][pc] = __saturatef(rr);
            G[pr][pc] = __saturatef(gg);
            B[pr][pc] = __saturatef(bb);
        }
    }

    float* __restrict__ o = out + (size_t)n * 3 * HW;
#pragma unroll
    for (int pr = 0; pr < 2; pr++) {
        const size_t base = (size_t)(row0 + pr) * W + col0;
        stcs4(o + 0 * (size_t)HW + base, R[pr][0], R[pr][1], R[pr][2], R[pr][3]);
        stcs4(o + 1 * (size_t)HW + base, G[pr][0], G[pr][1], G[pr][2], G[pr][3]);
        stcs4(o + 2 * (size_t)HW + base, B[pr][0], B[pr][1], B[pr][2], B[pr][3]);
    }
}

extern "C" void kernel_launch(void* const* d_in, const int* in_sizes, int n_in,
                              void* d_out, int out_size)
{
    const float* x = (const float*)d_in[0];   // (4,1,2048,2048) f32
    // d_in[1] (the 5x5 kernels) is a fixed constant -> hardcoded above.
    float* out = (float*)d_out;               // (4,3,2048,2048) f32

    dim3 block(32, 4, 1);                     // 128 threads: 128 cols x 8 rows per block
    dim3 grid(W / (4 * 32), H / (2 * 4), 4);  // (16, 256, 4)
    demosaic_kernel<<<grid, block>>>(x, out);
}

// round 4
// speedup vs baseline: 1.0622x; 1.0622x over previous
#include <cuda_runtime.h>

#define H 2048
#define W 2048
#define HW (H * W)

__device__ __forceinline__ int refl(int i, int n) {
    if (i < 0) return -i;
    if (i >= n) return 2 * n - 2 - i;
    return i;
}

// max 64 regs/thread (8 blocks/SM cap): keep the 6x12 window fully
// register-resident -> no local-memory spills, full MLP on the 18 LDG.128.
__global__ __launch_bounds__(128, 8) void demosaic_kernel(
    const float* __restrict__ x, float* __restrict__ out)
{
    const int tx = blockIdx.x * blockDim.x + threadIdx.x;  // 0..511  (4 cols each)
    const int ty = blockIdx.y * blockDim.y + threadIdx.y;  // 0..1023 (2 rows each)
    const int n  = blockIdx.z;                             // batch 0..3

    const int col0 = tx * 4;
    const int row0 = ty * 2;

    const float* __restrict__ xp = x + (size_t)n * HW;

    // Window: rows row0-2 .. row0+3 (6), cols col0-4 .. col0+7 (12, float4-aligned).
    float v[6][12];

    const bool interior = (row0 >= 2) && (row0 <= H - 6) &&
                          (col0 >= 4) && (col0 <= W - 8);

    if (interior) {
#pragma unroll
        for (int r = 0; r < 6; r++) {
            const float4* p = reinterpret_cast<const float4*>(
                xp + (size_t)(row0 - 2 + r) * W + (col0 - 4));
            float4 a = __ldg(p);
            float4 b = __ldg(p + 1);
            float4 c = __ldg(p + 2);
            v[r][0] = a.x; v[r][1] = a.y; v[r][2]  = a.z; v[r][3]  = a.w;
            v[r][4] = b.x; v[r][5] = b.y; v[r][6]  = b.z; v[r][7]  = b.w;
            v[r][8] = c.x; v[r][9] = c.y; v[r][10] = c.z; v[r][11] = c.w;
        }
    } else {
        // Border: scalar loads with reflect indexing (mode="reflect", no edge repeat).
#pragma unroll
        for (int r = 0; r < 6; r++) {
            const int rr = refl(row0 - 2 + r, H);
            const float* rowp = xp + (size_t)rr * W;
#pragma unroll
            for (int ci = 0; ci < 12; ci++) {
                const int cc = refl(col0 - 4 + ci, W);
                v[r][ci] = __ldg(rowp + cc);
            }
        }
    }

    // Demosaic 5x5 taps (all /8), factored into shared sub-sums:
    //   kgrb  = (4c + 2(v1+h1) - (v2+h2)) / 8
    //   krbbr = (6c + 2*diag - 1.5(v2+h2)) / 8
    //   krbg0 = (5c + 4h1 - diag + 0.5 v2 - h2) / 8
    //   krbg1 = (5c + 4v1 - diag + 0.5 h2 - v2) / 8
    float R[2][4], G[2][4], B[2][4];

#pragma unroll
    for (int pr = 0; pr < 2; pr++) {
#pragma unroll
        for (int pc = 0; pc < 4; pc++) {
            const int r = 2 + pr;
            const int c = 4 + pc;
            const float ctr = v[r][c];

            if ((pr & 1) == 0 && (pc & 1) == 0) {
                // R site: G=kgrb, B=krbbr
                const float v1 = v[r - 1][c] + v[r + 1][c];
                const float h1 = v[r][c - 1] + v[r][c + 1];
                const float ax2 = v[r - 2][c] + v[r + 2][c] + v[r][c - 2] + v[r][c + 2];
                const float dg = v[r - 1][c - 1] + v[r - 1][c + 1] +
                                 v[r + 1][c - 1] + v[r + 1][c + 1];
                R[pr][pc] = ctr;  // input already in [0,1]
                G[pr][pc] = __saturatef(0.125f * (4.0f * ctr + 2.0f * (v1 + h1) - ax2));
                B[pr][pc] = __saturatef(0.125f * (6.0f * ctr + 2.0f * dg - 1.5f * ax2));
            } else if ((pr & 1) == 0) {
                // G site on R row: R=krbg0, B=krbg1
                const float v1 = v[r - 1][c] + v[r + 1][c];
                const float h1 = v[r][c - 1] + v[r][c + 1];
                const float v2 = v[r - 2][c] + v[r + 2][c];
                const float h2 = v[r][c - 2] + v[r][c + 2];
                const float dg = v[r - 1][c - 1] + v[r - 1][c + 1] +
                                 v[r + 1][c - 1] + v[r + 1][c + 1];
                R[pr][pc] = __saturatef(0.125f * (5.0f * ctr + 4.0f * h1 - dg + 0.5f * v2 - h2));
                G[pr][pc] = ctr;
                B[pr][pc] = __saturatef(0.125f * (5.0f * ctr + 4.0f * v1 - dg + 0.5f * h2 - v2));
            } else if ((pc & 1) == 0) {
                // G site on B row: R=krbg1, B=krbg0
                const float v1 = v[r - 1][c] + v[r + 1][c];
                const float h1 = v[r][c - 1] + v[r][c + 1];
                const float v2 = v[r - 2][c] + v[r + 2][c];
                const float h2 = v[r][c - 2] + v[r][c + 2];
                const float dg = v[r - 1][c - 1] + v[r - 1][c + 1] +
                                 v[r + 1][c - 1] + v[r + 1][c + 1];
                R[pr][pc] = __saturatef(0.125f * (5.0f * ctr + 4.0f * v1 - dg + 0.5f * h2 - v2));
                G[pr][pc] = ctr;
                B[pr][pc] = __saturatef(0.125f * (5.0f * ctr + 4.0f * h1 - dg + 0.5f * v2 - h2));
            } else {
                // B site: R=krbbr, G=kgrb
                const float v1 = v[r - 1][c] + v[r + 1][c];
                const float h1 = v[r][c - 1] + v[r][c + 1];
                const float ax2 = v[r - 2][c] + v[r + 2][c] + v[r][c - 2] + v[r][c + 2];
                const float dg = v[r - 1][c - 1] + v[r - 1][c + 1] +
                                 v[r + 1][c - 1] + v[r + 1][c + 1];
                R[pr][pc] = __saturatef(0.125f * (6.0f * ctr + 2.0f * dg - 1.5f * ax2));
                G[pr][pc] = __saturatef(0.125f * (4.0f * ctr + 2.0f * (v1 + h1) - ax2));
                B[pr][pc] = ctr;
            }
        }
    }

    float* __restrict__ o = out + (size_t)n * 3 * HW;
#pragma unroll
    for (int pr = 0; pr < 2; pr++) {
        const size_t base = (size_t)(row0 + pr) * W + col0;
        *reinterpret_cast<float4*>(o + 0 * (size_t)HW + base) =
            make_float4(R[pr][0], R[pr][1], R[pr][2], R[pr][3]);
        *reinterpret_cast<float4*>(o + 1 * (size_t)HW + base) =
            make_float4(G[pr][0], G[pr][1], G[pr][2], G[pr][3]);
        *reinterpret_cast<float4*>(o + 2 * (size_t)HW + base) =
            make_float4(B[pr][0], B[pr][1], B[pr][2], B[pr][3]);
    }
}

extern "C" void kernel_launch(void* const* d_in, const int* in_sizes, int n_in,
                              void* d_out, int out_size)
{
    const float* x = (const float*)d_in[0];   // (4,1,2048,2048) f32
    // d_in[1] (the 5x5 kernels) is a fixed constant -> hardcoded above.
    float* out = (float*)d_out;               // (4,3,2048,2048) f32

    dim3 block(32, 4, 1);                     // 128 threads: 128 cols x 8 rows per block
    dim3 grid(W / (4 * 32), H / (2 * 4), 4);  // (16, 256, 4)
    demosaic_kernel<<<grid, block>>>(x, out);
}